// round 15
// baseline (speedup 1.0000x reference)
#include <cuda_runtime.h>
#include <math.h>
#include <stdint.h>

#define TOKENS 2048
#define HDIM   2048
#define H2DIM  1024
#define NE     16
#define NMOD   4
#define CAP    768
#define KD     2048

static constexpr long long C_OFF   = (long long)TOKENS * NE * CAP;
static constexpr long long RP_OFF  = 2 * C_OFF;
static constexpr long long AUX_OFF = RP_OFF + (long long)TOKENS * NE;

// ---------------- device scratch (tf32 hi/lo planes + fp32 buffers) ------------
#define M4 (4 * 1024 * 1024)
__device__ float g_HSh[M4],  g_HSl[M4];    // hs
__device__ float g_MIh[M4],  g_MIl[M4];    // mod_image
__device__ float g_MGh[M4],  g_MGl[M4];    // mod_genomic
__device__ float g_W1h[M4],  g_W1l[M4];    // Wm1
__device__ float g_Wg1h[M4], g_Wg1l[M4];   // Wg1
__device__ float g_W2h[M4],  g_W2l[M4];    // Wm2
__device__ float g_Ws1h[2 * M4], g_Ws1l[2 * M4];  // Ws1 (4 x 2048x1024)
__device__ float g_T1h[M4],  g_T1l[M4];    // relu(hs@Wm1+bm1), split at epilogue
__device__ float g_T2h[M4],  g_T2l[M4];    // missing_rep, split at epilogue
__device__ float g_T1g[M4];                // relu(hs@Wg1+bg1), fp32
__device__ float g_S1[NMOD * TOKENS * H2DIM];
__device__ float g_glog[TOKENS * NE];
__device__ float g_slog[NMOD * TOKENS * NE];
__device__ float g_partial[8 * NE];

struct SplitSlices {
    const float4* src[8];
    float4*       hi[8];
    float4*       lo[8];
};
struct GemmSlices {
    const float* Ah[6], *Al[6], *Bh[6], *Bl[6], *bias[6];
    float*       C[6];
    float*       Cl[6];   // non-null -> write tf32 split planes (C=hi, Cl=lo)
    int          N[6];
    int          bn0[6];
};
struct LogitsBatch {
    const float* X[5];
    const float* W[5];
    const float* bias[5];
    float*       out[5];
    int          Kd[5];
};

// ---------------- helpers ------------------------------------------------------
__device__ __forceinline__ void split2(float v, uint32_t& hb, uint32_t& lb) {
    asm("cvt.rna.tf32.f32 %0, %1;" : "=r"(hb) : "f"(v));
    float lo = v - __uint_as_float(hb);
    asm("cvt.rna.tf32.f32 %0, %1;" : "=r"(lb) : "f"(lo));
}

__device__ __forceinline__ void mma_tf32(float* c, const uint32_t* a, const uint32_t* b) {
    asm volatile(
        "mma.sync.aligned.m16n8k8.row.col.f32.tf32.tf32.f32 "
        "{%0,%1,%2,%3}, {%4,%5,%6,%7}, {%8,%9}, {%0,%1,%2,%3};"
        : "+f"(c[0]), "+f"(c[1]), "+f"(c[2]), "+f"(c[3])
        : "r"(a[0]), "r"(a[1]), "r"(a[2]), "r"(a[3]), "r"(b[0]), "r"(b[1]));
}

#define CP16(dst, src) \
    asm volatile("cp.async.cg.shared.global [%0], [%1], 16;" :: "r"(dst), "l"(src))
#define CP_COMMIT() asm volatile("cp.async.commit_group;" ::: "memory")
#define CP_WAIT1()  asm volatile("cp.async.wait_group 1;" ::: "memory")
#define CP_WAIT0()  asm volatile("cp.async.wait_group 0;" ::: "memory")

// ---------------- zero-fill -----------------------------------------------------
__global__ void zero_kernel(float4* __restrict__ p, int n4) {
    int i = blockIdx.x * blockDim.x + threadIdx.x;
    int stride = gridDim.x * blockDim.x;
    float4 z = make_float4(0.f, 0.f, 0.f, 0.f);
    for (; i < n4; i += stride) p[i] = z;
}

// ---------------- bulk tf32 split: 8 slots of 4M floats each --------------------
__global__ void split_b(SplitSlices ss) {
    const int z = blockIdx.z;
    const float4* __restrict__ src = ss.src[z];
    float4* __restrict__ hi = ss.hi[z];
    float4* __restrict__ lo = ss.lo[z];
    const int n4 = M4 / 4;
    int i = blockIdx.x * blockDim.x + threadIdx.x;
    int stride = gridDim.x * blockDim.x;
    for (; i < n4; i += stride) {
        float4 v = src[i];
        uint4 h, l;
        split2(v.x, h.x, l.x); split2(v.y, h.y, l.y);
        split2(v.z, h.z, l.z); split2(v.w, h.w, l.w);
        hi[i] = *(float4*)&h;
        lo[i] = *(float4*)&l;
    }
}

// ---------------- HMMA 3xTF32 GEMM, 128x128 tile, 3-stage cp.async -------------
// C = act(A @ W + bias). 128x128 CTA tile, BK=32, 256 threads (8 warps, 64x32
// warp tiles; 1 CTA/SM). Pre-split tf32 planes; producer = 16 cp.async/thread.
// Stage (words): Ah[128][36]=4608, Al=4608, Bh[32][136]=4352, Bl=4352 -> 17920.
// 3 stages = 215040 B. wait_group 1 -> each stage has ~2 MMA phases of lead.
#define AL_OFS 4608
#define BH_OFS 9216
#define BL_OFS 13568
#define STG_W  17920
#define STG_B  (STG_W * 4)
#define SMEM_BYTES (3 * STG_B)   // 215040

__global__ __launch_bounds__(256, 1) void gemm_ps(GemmSlices gs, int do_relu)
{
    extern __shared__ uint32_t sm[];

    const int z = blockIdx.z;
    const float* __restrict__ Ahg  = gs.Ah[z];
    const float* __restrict__ Alg  = gs.Al[z];
    const float* __restrict__ Bhg  = gs.Bh[z];
    const float* __restrict__ Blg  = gs.Bl[z];
    const float* __restrict__ bias = gs.bias[z];
    float* __restrict__ Cg         = gs.C[z];
    float* __restrict__ Clg        = gs.Cl[z];
    const int N  = gs.N[z];
    const int bn = gs.bn0[z] + blockIdx.x * 128;
    const int bm = blockIdx.y * 128;

    const int tid  = threadIdx.x;
    const int wid  = tid >> 5;
    const int lane = tid & 31;
    const int gid  = lane >> 2;
    const int tig  = lane & 3;
    const int wm   = (wid & 1) * 64;
    const int wn   = (wid >> 1) * 32;

    const uint32_t smb = (uint32_t)__cvta_generic_to_shared(sm);

#define ISSUE_STAGE(s, kb) do {                                                  \
    uint32_t sb = smb + (uint32_t)(s) * STG_B;                                   \
    size_t ka = (size_t)(kb) * 32;                                               \
    _Pragma("unroll")                                                            \
    for (int l = 0; l < 4; l++) {                                                \
        int c = tid + 256 * l;                                                   \
        int r = c >> 3, o = (c & 7) * 4;                                         \
        uint32_t d = sb + (uint32_t)(r * 36 + o) * 4;                            \
        size_t go = (size_t)(bm + r) * KD + ka + o;                              \
        CP16(d, Ahg + go);                                                       \
        CP16(d + AL_OFS * 4, Alg + go);                                          \
    }                                                                            \
    _Pragma("unroll")                                                            \
    for (int l = 0; l < 4; l++) {                                                \
        int c = tid + 256 * l;                                                   \
        int r = c >> 5, o = (c & 31) * 4;                                        \
        uint32_t d = sb + BH_OFS * 4 + (uint32_t)(r * 136 + o) * 4;              \
        size_t go = (size_t)(ka + r) * N + bn + o;                               \
        CP16(d, Bhg + go);                                                       \
        CP16(d + (BL_OFS - BH_OFS) * 4, Blg + go);                               \
    }                                                                            \
    CP_COMMIT();                                                                 \
} while (0)

#define MMA_K0(k0) do {                                                          \
    uint32_t fa[4][4], fa2[4][4], fb[4][2];                                      \
    _Pragma("unroll")                                                            \
    for (int mt = 0; mt < 4; mt++) {                                             \
        int rbase = (wm + mt * 16 + gid) * 36 + (k0) + tig;                      \
        fa[mt][0] = Ah[rbase];                                                   \
        fa[mt][1] = Ah[rbase + 8 * 36];                                          \
        fa[mt][2] = Ah[rbase + 4];                                               \
        fa[mt][3] = Ah[rbase + 8 * 36 + 4];                                      \
    }                                                                            \
    _Pragma("unroll")                                                            \
    for (int nt = 0; nt < 4; nt++) {                                             \
        int cbase = ((k0) + tig) * 136 + wn + nt * 8 + gid;                      \
        fb[nt][0] = Bh[cbase];                                                   \
        fb[nt][1] = Bh[cbase + 4 * 136];                                         \
    }                                                                            \
    _Pragma("unroll")                                                            \
    for (int mt = 0; mt < 4; mt++)                                               \
        _Pragma("unroll")                                                        \
        for (int nt = 0; nt < 4; nt++)                                           \
            mma_tf32(acc[mt][nt], fa[mt], fb[nt]);                               \
    _Pragma("unroll")                                                            \
    for (int mt = 0; mt < 4; mt++) {                                             \
        int rbase = (wm + mt * 16 + gid) * 36 + (k0) + tig;                      \
        fa2[mt][0] = Al[rbase];                                                  \
        fa2[mt][1] = Al[rbase + 8 * 36];                                         \
        fa2[mt][2] = Al[rbase + 4];                                              \
        fa2[mt][3] = Al[rbase + 8 * 36 + 4];                                     \
    }                                                                            \
    _Pragma("unroll")                                                            \
    for (int mt = 0; mt < 4; mt++)                                               \
        _Pragma("unroll")                                                        \
        for (int nt = 0; nt < 4; nt++)                                           \
            mma_tf32(acc[mt][nt], fa2[mt], fb[nt]);                              \
    _Pragma("unroll")                                                            \
    for (int nt = 0; nt < 4; nt++) {                                             \
        int cbase = ((k0) + tig) * 136 + wn + nt * 8 + gid;                      \
        fb[nt][0] = Bl[cbase];                                                   \
        fb[nt][1] = Bl[cbase + 4 * 136];                                         \
    }                                                                            \
    _Pragma("unroll")                                                            \
    for (int mt = 0; mt < 4; mt++)                                               \
        _Pragma("unroll")                                                        \
        for (int nt = 0; nt < 4; nt++)                                           \
            mma_tf32(acc[mt][nt], fa[mt], fb[nt]);                               \
} while (0)

    float acc[4][4][4];
#pragma unroll
    for (int mt = 0; mt < 4; mt++)
#pragma unroll
        for (int nt = 0; nt < 4; nt++)
#pragma unroll
            for (int r = 0; r < 4; r++) acc[mt][nt][r] = 0.f;

    const int KT = KD / 32;   // 64

    // prologue: stages 0,1 in flight
    ISSUE_STAGE(0, 0);
    ISSUE_STAGE(1, 1);

    for (int kb = 0; kb < KT; kb++) {
        if (kb < KT - 1) { CP_WAIT1(); } else { CP_WAIT0(); }
        __syncthreads();

        // issue stage kb+2 into buffer (kb+2)%3 (old content consumed in iter kb-1)
        if (kb + 2 < KT) {
            int s = (kb + 2) % 3;
            ISSUE_STAGE(s, kb + 2);
        }

        const uint32_t* st = sm + (kb % 3) * STG_W;
        const uint32_t* Ah = st;
        const uint32_t* Al = st + AL_OFS;
        const uint32_t* Bh = st + BH_OFS;
        const uint32_t* Bl = st + BL_OFS;

        MMA_K0(0);
        MMA_K0(8);
        MMA_K0(16);
        MMA_K0(24);

        __syncthreads();
    }

    // ---- epilogue: bias + relu, then fp32 store or tf32 split store ----
    const bool do_split = (Clg != nullptr);
#pragma unroll
    for (int nt = 0; nt < 4; nt++) {
        int col = bn + wn + nt * 8 + 2 * tig;
        float b0 = bias[col], b1 = bias[col + 1];
#pragma unroll
        for (int mt = 0; mt < 4; mt++) {
            int row = bm + wm + mt * 16 + gid;
            float v0 = acc[mt][nt][0] + b0;
            float v1 = acc[mt][nt][1] + b1;
            float v2 = acc[mt][nt][2] + b0;
            float v3 = acc[mt][nt][3] + b1;
            if (do_relu) {
                v0 = fmaxf(v0, 0.f); v1 = fmaxf(v1, 0.f);
                v2 = fmaxf(v2, 0.f); v3 = fmaxf(v3, 0.f);
            }
            size_t o0 = (size_t)row * N + col;
            size_t o1 = (size_t)(row + 8) * N + col;
            if (do_split) {
                uint32_t h0, l0, h1, l1, h2, l2, h3, l3;
                split2(v0, h0, l0); split2(v1, h1, l1);
                split2(v2, h2, l2); split2(v3, h3, l3);
                *(float2*)(Cg  + o0) = make_float2(__uint_as_float(h0), __uint_as_float(h1));
                *(float2*)(Cg  + o1) = make_float2(__uint_as_float(h2), __uint_as_float(h3));
                *(float2*)(Clg + o0) = make_float2(__uint_as_float(l0), __uint_as_float(l1));
                *(float2*)(Clg + o1) = make_float2(__uint_as_float(l2), __uint_as_float(l3));
            } else {
                *(float2*)(Cg + o0) = make_float2(v0, v1);
                *(float2*)(Cg + o1) = make_float2(v2, v3);
            }
        }
    }
#undef ISSUE_STAGE
#undef MMA_K0
}

// ---------------- logits: warp-per-token, z-batched (5 slots) ------------------
__global__ __launch_bounds__(128) void logits_b(LogitsBatch lb)
{
    __shared__ float wt[NE][257];
    const int z = blockIdx.z;
    const float* __restrict__ X    = lb.X[z];
    const float* __restrict__ W    = lb.W[z];
    const float* __restrict__ bias = lb.bias[z];
    float* __restrict__ out        = lb.out[z];
    const int Kd = lb.Kd[z];

    const int tid = threadIdx.x;
    const int wid = tid >> 5;
    const int lane = tid & 31;
    const int tok = blockIdx.x * 4 + wid;

    float acc[NE];
#pragma unroll
    for (int e = 0; e < NE; e++) acc[e] = 0.f;

    const float* xrow = X + (size_t)tok * Kd;

    for (int c = 0; c < Kd; c += 256) {
#pragma unroll
        for (int l = 0; l < 8; l++) {
            int id = tid + l * 128;
            int k  = id >> 2;
            int e4 = (id & 3) << 2;
            float4 v = *(const float4*)(W + (size_t)(c + k) * NE + e4);
            wt[e4 + 0][k] = v.x;
            wt[e4 + 1][k] = v.y;
            wt[e4 + 2][k] = v.z;
            wt[e4 + 3][k] = v.w;
        }
        __syncthreads();
#pragma unroll
        for (int i = 0; i < 8; i++) {
            int kk = i * 32 + lane;
            float xv = xrow[c + kk];
#pragma unroll
            for (int e = 0; e < NE; e++)
                acc[e] = fmaf(xv, wt[e][kk], acc[e]);
        }
        __syncthreads();
    }
#pragma unroll
    for (int off = 16; off > 0; off >>= 1)
#pragma unroll
        for (int e = 0; e < NE; e++)
            acc[e] += __shfl_xor_sync(0xffffffffu, acc[e], off);
    if (lane == 0) {
#pragma unroll
        for (int e = 0; e < NE; e++)
            out[(size_t)tok * NE + e] = acc[e] + bias[e];
    }
}

// ---------------- router --------------------------------------------------------
__global__ __launch_bounds__(256) void router_kernel(
    const float* __restrict__ glog, const float* __restrict__ slog,
    float* __restrict__ out, float* __restrict__ partial)
{
    __shared__ float sh[256][NE];
    const int tid = threadIdx.x;
    const int tok = blockIdx.x * 256 + tid;

    float probs[NE];
    {
        float g[NE];
#pragma unroll
        for (int i = 0; i < NE; i++) g[i] = glog[(size_t)tok * NE + i];
        float mx = g[0];
#pragma unroll
        for (int i = 1; i < NE; i++) mx = fmaxf(mx, g[i]);
        float s = 0.f;
#pragma unroll
        for (int i = 0; i < NE; i++) { g[i] = expf(g[i] - mx); s += g[i]; }
        float inv = 0.7f / s;
#pragma unroll
        for (int i = 0; i < NE; i++) probs[i] = g[i] * inv;
    }
#pragma unroll
    for (int m = 0; m < NMOD; m++) {
        float g[NE];
#pragma unroll
        for (int i = 0; i < NE; i++)
            g[i] = slog[((size_t)m * TOKENS + tok) * NE + i];
        float mx = g[0];
#pragma unroll
        for (int i = 1; i < NE; i++) mx = fmaxf(mx, g[i]);
        float s = 0.f;
#pragma unroll
        for (int i = 0; i < NE; i++) { g[i] = expf(g[i] - mx); s += g[i]; }
        float inv = 0.15f / s;
#pragma unroll
        for (int i = 0; i < NE; i++) probs[i] += g[i] * inv;
    }

#pragma unroll
    for (int i = 0; i < NE; i++)
        out[RP_OFF + (size_t)tok * NE + i] = probs[i];

    unsigned used = 0;
    int idx[4]; float val[4]; float vsum = 0.f;
#pragma unroll
    for (int k = 0; k < 4; k++) {
        float best = -1.f; int bi = 0;
#pragma unroll
        for (int i = 0; i < NE; i++) {
            bool ok = !((used >> i) & 1u);
            if (ok && probs[i] > best) { best = probs[i]; bi = i; }
        }
        used |= (1u << bi);
        idx[k] = bi; val[k] = best; vsum += best;
    }
    float invv = 1.f / vsum;
#pragma unroll
    for (int k = 0; k < 4; k++) {
        size_t base = ((size_t)tok * NE + idx[k]) * CAP;
        out[base]         = 1.f;
        out[C_OFF + base] = val[k] * invv;
    }

#pragma unroll
    for (int i = 0; i < NE; i++) sh[tid][i] = probs[i];
    __syncthreads();
    if (tid < NE) {
        float s = 0.f;
        for (int i = 0; i < 256; i++) s += sh[i][tid];
        partial[blockIdx.x * NE + tid] = s;
    }
}

// ---------------- aux loss ------------------------------------------------------
__global__ void aux_kernel(const float* __restrict__ partial, float* __restrict__ out)
{
    const int tid = threadIdx.x;
    float v = 0.f;
    if (tid < NE) {
        float s = 0.f;
#pragma unroll
        for (int b = 0; b < 8; b++) s += partial[b * NE + tid];
        float mp = s * (1.f / (float)TOKENS);
        v = mp * logf(mp * (float)NE + 1e-9f);
    }
#pragma unroll
    for (int off = 16; off > 0; off >>= 1)
        v += __shfl_down_sync(0xffffffffu, v, off);
    if (tid == 0) out[AUX_OFF] = v;
}

// ---------------- launch --------------------------------------------------------
extern "C" void kernel_launch(void* const* d_in, const int* in_sizes, int n_in,
                              void* d_out, int out_size)
{
    const float* hs   = (const float*)d_in[0];
    const float* mimg = (const float*)d_in[1];
    const float* mgen = (const float*)d_in[2];
    const float* Wg1  = (const float*)d_in[3];
    const float* bg1  = (const float*)d_in[4];
    const float* Wg2  = (const float*)d_in[5];
    const float* bg2  = (const float*)d_in[6];
    const float* Wm1  = (const float*)d_in[7];
    const float* bm1  = (const float*)d_in[8];
    const float* Wm2  = (const float*)d_in[9];
    const float* bm2  = (const float*)d_in[10];
    const float* Ws1  = (const float*)d_in[11];
    const float* bs1  = (const float*)d_in[12];
    const float* Ws2  = (const float*)d_in[13];
    const float* bs2  = (const float*)d_in[14];
    float* out = (float*)d_out;

    float *HSh, *HSl, *MIh, *MIl, *MGh, *MGl;
    float *W1h, *W1l, *Wg1h, *Wg1l, *W2h, *W2l, *Ws1h, *Ws1l;
    float *T1h, *T1l, *T2h, *T2l, *T1g, *S1, *glog, *slog, *partial;
    cudaGetSymbolAddress((void**)&HSh,  g_HSh);  cudaGetSymbolAddress((void**)&HSl,  g_HSl);
    cudaGetSymbolAddress((void**)&MIh,  g_MIh);  cudaGetSymbolAddress((void**)&MIl,  g_MIl);
    cudaGetSymbolAddress((void**)&MGh,  g_MGh);  cudaGetSymbolAddress((void**)&MGl,  g_MGl);
    cudaGetSymbolAddress((void**)&W1h,  g_W1h);  cudaGetSymbolAddress((void**)&W1l,  g_W1l);
    cudaGetSymbolAddress((void**)&Wg1h, g_Wg1h); cudaGetSymbolAddress((void**)&Wg1l, g_Wg1l);
    cudaGetSymbolAddress((void**)&W2h,  g_W2h);  cudaGetSymbolAddress((void**)&W2l,  g_W2l);
    cudaGetSymbolAddress((void**)&Ws1h, g_Ws1h); cudaGetSymbolAddress((void**)&Ws1l, g_Ws1l);
    cudaGetSymbolAddress((void**)&T1h,  g_T1h);  cudaGetSymbolAddress((void**)&T1l,  g_T1l);
    cudaGetSymbolAddress((void**)&T2h,  g_T2h);  cudaGetSymbolAddress((void**)&T2l,  g_T2l);
    cudaGetSymbolAddress((void**)&T1g,  g_T1g);
    cudaGetSymbolAddress((void**)&S1,   g_S1);
    cudaGetSymbolAddress((void**)&glog, g_glog);
    cudaGetSymbolAddress((void**)&slog, g_slog);
    cudaGetSymbolAddress((void**)&partial, g_partial);

    cudaFuncSetAttribute(gemm_ps,
                         cudaFuncAttributeMaxDynamicSharedMemorySize, SMEM_BYTES);

    zero_kernel<<<4096, 256>>>((float4*)out, (int)(2 * C_OFF / 4));

    // 0. bulk split of all inputs (8 slots x 4M floats)
    {
        SplitSlices ss{};
        ss.src[0] = (const float4*)hs;   ss.hi[0] = (float4*)HSh;  ss.lo[0] = (float4*)HSl;
        ss.src[1] = (const float4*)mimg; ss.hi[1] = (float4*)MIh;  ss.lo[1] = (float4*)MIl;
        ss.src[2] = (const float4*)mgen; ss.hi[2] = (float4*)MGh;  ss.lo[2] = (float4*)MGl;
        ss.src[3] = (const float4*)Wm1;  ss.hi[3] = (float4*)W1h;  ss.lo[3] = (float4*)W1l;
        ss.src[4] = (const float4*)Wg1;  ss.hi[4] = (float4*)Wg1h; ss.lo[4] = (float4*)Wg1l;
        ss.src[5] = (const float4*)Wm2;  ss.hi[5] = (float4*)W2h;  ss.lo[5] = (float4*)W2l;
        ss.src[6] = (const float4*)Ws1;  ss.hi[6] = (float4*)Ws1h; ss.lo[6] = (float4*)Ws1l;
        ss.src[7] = (const float4*)(Ws1 + M4);
        ss.hi[7]  = (float4*)(Ws1h + M4);
        ss.lo[7]  = (float4*)(Ws1l + M4);
        dim3 grid(1024, 1, 8);
        split_b<<<grid, 256>>>(ss);
    }

    // L1: big1 (HS@Wm1 -> T1 split) x2 col-slices, big3 (HS@Wg1 -> T1g) x2, mid0, mid1.
    // All slices are 2048 x 1024 outputs -> grid (8, 16, 6).
    {
        GemmSlices gs{};
        gs.Ah[0] = HSh; gs.Al[0] = HSl; gs.Bh[0] = W1h; gs.Bl[0] = W1l;
        gs.bias[0] = bm1; gs.C[0] = T1h; gs.Cl[0] = T1l; gs.N[0] = HDIM; gs.bn0[0] = 0;
        gs.Ah[1] = HSh; gs.Al[1] = HSl; gs.Bh[1] = W1h; gs.Bl[1] = W1l;
        gs.bias[1] = bm1; gs.C[1] = T1h; gs.Cl[1] = T1l; gs.N[1] = HDIM; gs.bn0[1] = 1024;
        gs.Ah[2] = HSh; gs.Al[2] = HSl; gs.Bh[2] = Wg1h; gs.Bl[2] = Wg1l;
        gs.bias[2] = bg1; gs.C[2] = T1g; gs.Cl[2] = nullptr; gs.N[2] = HDIM; gs.bn0[2] = 0;
        gs.Ah[3] = HSh; gs.Al[3] = HSl; gs.Bh[3] = Wg1h; gs.Bl[3] = Wg1l;
        gs.bias[3] = bg1; gs.C[3] = T1g; gs.Cl[3] = nullptr; gs.N[3] = HDIM; gs.bn0[3] = 1024;
        gs.Ah[4] = MIh; gs.Al[4] = MIl; gs.Bh[4] = Ws1h; gs.Bl[4] = Ws1l;
        gs.bias[4] = bs1; gs.C[4] = S1; gs.Cl[4] = nullptr; gs.N[4] = H2DIM; gs.bn0[4] = 0;
        gs.Ah[5] = MGh; gs.Al[5] = MGl;
        gs.Bh[5] = Ws1h + (size_t)HDIM * H2DIM; gs.Bl[5] = Ws1l + (size_t)HDIM * H2DIM;
        gs.bias[5] = bs1 + H2DIM; gs.C[5] = S1 + (size_t)TOKENS * H2DIM;
        gs.Cl[5] = nullptr; gs.N[5] = H2DIM; gs.bn0[5] = 0;
        dim3 grid(8, 16, 6);
        gemm_ps<<<grid, 256, SMEM_BYTES>>>(gs, 1);
    }

    // L2: T2 = T1 @ Wm2 + bm2 (no relu) -> split planes. 2 column slices.
    {
        GemmSlices gs{};
        for (int s = 0; s < 2; s++) {
            gs.Ah[s] = T1h; gs.Al[s] = T1l; gs.Bh[s] = W2h; gs.Bl[s] = W2l;
            gs.bias[s] = bm2; gs.C[s] = T2h; gs.Cl[s] = T2l;
            gs.N[s] = HDIM; gs.bn0[s] = s * 1024;
        }
        dim3 grid(8, 16, 2);
        gemm_ps<<<grid, 256, SMEM_BYTES>>>(gs, 0);
    }

    // L3: mid2, mid3 (A = T2 planes) -> S1 fp32. relu=1.
    {
        GemmSlices gs{};
        for (int m = 2; m < 4; m++) {
            int zz = m - 2;
            gs.Ah[zz] = T2h; gs.Al[zz] = T2l;
            gs.Bh[zz] = Ws1h + (size_t)m * HDIM * H2DIM;
            gs.Bl[zz] = Ws1l + (size_t)m * HDIM * H2DIM;
            gs.bias[zz] = bs1 + (size_t)m * H2DIM;
            gs.C[zz]  = S1 + (size_t)m * TOKENS * H2DIM;
            gs.Cl[zz] = nullptr;
            gs.N[zz]  = H2DIM;
            gs.bn0[zz] = 0;
        }
        dim3 grid(8, 16, 2);
        gemm_ps<<<grid, 256, SMEM_BYTES>>>(gs, 1);
    }

    // L4: all 5 logits GEMMs in one launch
    {
        LogitsBatch lb{};
        lb.X[0] = T1g; lb.W[0] = Wg2; lb.bias[0] = bg2; lb.out[0] = glog;
        lb.Kd[0] = HDIM;
        for (int m = 0; m < 4; m++) {
            lb.X[m+1]    = S1 + (size_t)m * TOKENS * H2DIM;
            lb.W[m+1]    = Ws2 + (size_t)m * H2DIM * NE;
            lb.bias[m+1] = bs2 + (size_t)m * NE;
            lb.out[m+1]  = slog + (size_t)m * TOKENS * NE;
            lb.Kd[m+1]   = H2DIM;
        }
        dim3 grid(512, 1, 5);
        logits_b<<<grid, 128>>>(lb);
    }

    router_kernel<<<8, 256>>>(glog, slog, out, partial);
    aux_kernel<<<1, 32>>>(partial, out);
}

// round 16
// speedup vs baseline: 1.0022x; 1.0022x over previous
#include <cuda_runtime.h>
#include <math.h>
#include <stdint.h>

#define TOKENS 2048
#define HDIM   2048
#define H2DIM  1024
#define NE     16
#define NMOD   4
#define CAP    768
#define KD     2048

static constexpr long long C_OFF   = (long long)TOKENS * NE * CAP;
static constexpr long long RP_OFF  = 2 * C_OFF;
static constexpr long long AUX_OFF = RP_OFF + (long long)TOKENS * NE;

// ---------------- device scratch (tf32 hi/lo planes + fp32 buffers) ------------
#define M4 (4 * 1024 * 1024)
__device__ float g_HSh[M4],  g_HSl[M4];    // hs
__device__ float g_MIh[M4],  g_MIl[M4];    // mod_image
__device__ float g_MGh[M4],  g_MGl[M4];    // mod_genomic
__device__ float g_W1h[M4],  g_W1l[M4];    // Wm1
__device__ float g_Wg1h[M4], g_Wg1l[M4];   // Wg1
__device__ float g_W2h[M4],  g_W2l[M4];    // Wm2
__device__ float g_Ws1h[2 * M4], g_Ws1l[2 * M4];  // Ws1 (4 x 2048x1024)
__device__ float g_T1h[M4],  g_T1l[M4];    // relu(hs@Wm1+bm1), split at epilogue
__device__ float g_T2h[M4],  g_T2l[M4];    // missing_rep, split at epilogue
__device__ float g_T1g[M4];                // relu(hs@Wg1+bg1), fp32
__device__ float g_S1[NMOD * TOKENS * H2DIM];
__device__ float g_glog[TOKENS * NE];
__device__ float g_slog[NMOD * TOKENS * NE];
__device__ float g_partial[8 * NE];

struct SplitSlices {
    const float4* src[8];
    float4*       hi[8];
    float4*       lo[8];
};
struct GemmSlices {
    const float* Ah[6], *Al[6], *Bh[6], *Bl[6], *bias[6];
    float*       C[6];
    float*       Cl[6];   // non-null -> write tf32 split planes (C=hi, Cl=lo)
    int          N[6];
    int          bn0[6];
};
struct LogitsBatch {
    const float* X[5];
    const float* W[5];
    const float* bias[5];
    float*       out[5];
    int          Kd[5];
};

// ---------------- helpers ------------------------------------------------------
__device__ __forceinline__ void split2(float v, uint32_t& hb, uint32_t& lb) {
    asm("cvt.rna.tf32.f32 %0, %1;" : "=r"(hb) : "f"(v));
    float lo = v - __uint_as_float(hb);
    asm("cvt.rna.tf32.f32 %0, %1;" : "=r"(lb) : "f"(lo));
}

__device__ __forceinline__ void mma_tf32(float* c, const uint32_t* a, const uint32_t* b) {
    asm volatile(
        "mma.sync.aligned.m16n8k8.row.col.f32.tf32.tf32.f32 "
        "{%0,%1,%2,%3}, {%4,%5,%6,%7}, {%8,%9}, {%0,%1,%2,%3};"
        : "+f"(c[0]), "+f"(c[1]), "+f"(c[2]), "+f"(c[3])
        : "r"(a[0]), "r"(a[1]), "r"(a[2]), "r"(a[3]), "r"(b[0]), "r"(b[1]));
}

#define CP16(dst, src) \
    asm volatile("cp.async.cg.shared.global [%0], [%1], 16;" :: "r"(dst), "l"(src))
#define CP_COMMIT() asm volatile("cp.async.commit_group;" ::: "memory")
#define CP_WAIT1()  asm volatile("cp.async.wait_group 1;" ::: "memory")
#define CP_WAIT0()  asm volatile("cp.async.wait_group 0;" ::: "memory")

// ---------------- zero-fill -----------------------------------------------------
__global__ void zero_kernel(float4* __restrict__ p, int n4) {
    int i = blockIdx.x * blockDim.x + threadIdx.x;
    int stride = gridDim.x * blockDim.x;
    float4 z = make_float4(0.f, 0.f, 0.f, 0.f);
    for (; i < n4; i += stride) p[i] = z;
}

// ---------------- bulk tf32 split: 8 slots of 4M floats each --------------------
__global__ void split_b(SplitSlices ss) {
    const int z = blockIdx.z;
    const float4* __restrict__ src = ss.src[z];
    float4* __restrict__ hi = ss.hi[z];
    float4* __restrict__ lo = ss.lo[z];
    const int n4 = M4 / 4;
    int i = blockIdx.x * blockDim.x + threadIdx.x;
    int stride = gridDim.x * blockDim.x;
    for (; i < n4; i += stride) {
        float4 v = src[i];
        uint4 h, l;
        split2(v.x, h.x, l.x); split2(v.y, h.y, l.y);
        split2(v.z, h.z, l.z); split2(v.w, h.w, l.w);
        hi[i] = *(float4*)&h;
        lo[i] = *(float4*)&l;
    }
}

// ---------------- HMMA 3xTF32 GEMM, 128x128 tile, 3-stage cp.async -------------
// C = act(A @ W + bias). 128x128 CTA tile, BK=32, 256 threads (8 warps, 64x32
// warp tiles; 1 CTA/SM). Pre-split tf32 planes; producer = 16 cp.async/thread.
// Stage (words): Ah[128][36]=4608, Al=4608, Bh[32][136]=4352, Bl=4352 -> 17920.
// 3 stages = 215040 B. wait_group 1 -> each stage has ~2 MMA phases of lead.
#define AL_OFS 4608
#define BH_OFS 9216
#define BL_OFS 13568
#define STG_W  17920
#define STG_B  (STG_W * 4)
#define SMEM_BYTES (3 * STG_B)   // 215040

__global__ __launch_bounds__(256, 1) void gemm_ps(GemmSlices gs, int do_relu)
{
    extern __shared__ uint32_t sm[];

    const int z = blockIdx.z;
    const float* __restrict__ Ahg  = gs.Ah[z];
    const float* __restrict__ Alg  = gs.Al[z];
    const float* __restrict__ Bhg  = gs.Bh[z];
    const float* __restrict__ Blg  = gs.Bl[z];
    const float* __restrict__ bias = gs.bias[z];
    float* __restrict__ Cg         = gs.C[z];
    float* __restrict__ Clg        = gs.Cl[z];
    const int N  = gs.N[z];
    const int bn = gs.bn0[z] + blockIdx.x * 128;
    const int bm = blockIdx.y * 128;

    const int tid  = threadIdx.x;
    const int wid  = tid >> 5;
    const int lane = tid & 31;
    const int gid  = lane >> 2;
    const int tig  = lane & 3;
    const int wm   = (wid & 1) * 64;
    const int wn   = (wid >> 1) * 32;

    const uint32_t smb = (uint32_t)__cvta_generic_to_shared(sm);

#define ISSUE_STAGE(s, kb) do {                                                  \
    uint32_t sb = smb + (uint32_t)(s) * STG_B;                                   \
    size_t ka = (size_t)(kb) * 32;                                               \
    _Pragma("unroll")                                                            \
    for (int l = 0; l < 4; l++) {                                                \
        int c = tid + 256 * l;                                                   \
        int r = c >> 3, o = (c & 7) * 4;                                         \
        uint32_t d = sb + (uint32_t)(r * 36 + o) * 4;                            \
        size_t go = (size_t)(bm + r) * KD + ka + o;                              \
        CP16(d, Ahg + go);                                                       \
        CP16(d + AL_OFS * 4, Alg + go);                                          \
    }                                                                            \
    _Pragma("unroll")                                                            \
    for (int l = 0; l < 4; l++) {                                                \
        int c = tid + 256 * l;                                                   \
        int r = c >> 5, o = (c & 31) * 4;                                        \
        uint32_t d = sb + BH_OFS * 4 + (uint32_t)(r * 136 + o) * 4;              \
        size_t go = (size_t)(ka + r) * N + bn + o;                               \
        CP16(d, Bhg + go);                                                       \
        CP16(d + (BL_OFS - BH_OFS) * 4, Blg + go);                               \
    }                                                                            \
    CP_COMMIT();                                                                 \
} while (0)

#define MMA_K0(k0) do {                                                          \
    uint32_t fa[4][4], fa2[4][4], fb[4][2];                                      \
    _Pragma("unroll")                                                            \
    for (int mt = 0; mt < 4; mt++) {                                             \
        int rbase = (wm + mt * 16 + gid) * 36 + (k0) + tig;                      \
        fa[mt][0] = Ah[rbase];                                                   \
        fa[mt][1] = Ah[rbase + 8 * 36];                                          \
        fa[mt][2] = Ah[rbase + 4];                                               \
        fa[mt][3] = Ah[rbase + 8 * 36 + 4];                                      \
    }                                                                            \
    _Pragma("unroll")                                                            \
    for (int nt = 0; nt < 4; nt++) {                                             \
        int cbase = ((k0) + tig) * 136 + wn + nt * 8 + gid;                      \
        fb[nt][0] = Bh[cbase];                                                   \
        fb[nt][1] = Bh[cbase + 4 * 136];                                         \
    }                                                                            \
    _Pragma("unroll")                                                            \
    for (int mt = 0; mt < 4; mt++)                                               \
        _Pragma("unroll")                                                        \
        for (int nt = 0; nt < 4; nt++)                                           \
            mma_tf32(acc[mt][nt], fa[mt], fb[nt]);                               \
    _Pragma("unroll")                                                            \
    for (int mt = 0; mt < 4; mt++) {                                             \
        int rbase = (wm + mt * 16 + gid) * 36 + (k0) + tig;                      \
        fa2[mt][0] = Al[rbase];                                                  \
        fa2[mt][1] = Al[rbase + 8 * 36];                                         \
        fa2[mt][2] = Al[rbase + 4];                                              \
        fa2[mt][3] = Al[rbase + 8 * 36 + 4];                                     \
    }                                                                            \
    _Pragma("unroll")                                                            \
    for (int mt = 0; mt < 4; mt++)                                               \
        _Pragma("unroll")                                                        \
        for (int nt = 0; nt < 4; nt++)                                           \
            mma_tf32(acc[mt][nt], fa2[mt], fb[nt]);                              \
    _Pragma("unroll")                                                            \
    for (int nt = 0; nt < 4; nt++) {                                             \
        int cbase = ((k0) + tig) * 136 + wn + nt * 8 + gid;                      \
        fb[nt][0] = Bl[cbase];                                                   \
        fb[nt][1] = Bl[cbase + 4 * 136];                                         \
    }                                                                            \
    _Pragma("unroll")                                                            \
    for (int mt = 0; mt < 4; mt++)                                               \
        _Pragma("unroll")                                                        \
        for (int nt = 0; nt < 4; nt++)                                           \
            mma_tf32(acc[mt][nt], fa[mt], fb[nt]);                               \
} while (0)

    float acc[4][4][4];
#pragma unroll
    for (int mt = 0; mt < 4; mt++)
#pragma unroll
        for (int nt = 0; nt < 4; nt++)
#pragma unroll
            for (int r = 0; r < 4; r++) acc[mt][nt][r] = 0.f;

    const int KT = KD / 32;   // 64

    // prologue: stages 0,1 in flight
    ISSUE_STAGE(0, 0);
    ISSUE_STAGE(1, 1);

    for (int kb = 0; kb < KT; kb++) {
        if (kb < KT - 1) { CP_WAIT1(); } else { CP_WAIT0(); }
        __syncthreads();

        // issue stage kb+2 into buffer (kb+2)%3 (old content consumed in iter kb-1)
        if (kb + 2 < KT) {
            int s = (kb + 2) % 3;
            ISSUE_STAGE(s, kb + 2);
        }

        const uint32_t* st = sm + (kb % 3) * STG_W;
        const uint32_t* Ah = st;
        const uint32_t* Al = st + AL_OFS;
        const uint32_t* Bh = st + BH_OFS;
        const uint32_t* Bl = st + BL_OFS;

        MMA_K0(0);
        MMA_K0(8);
        MMA_K0(16);
        MMA_K0(24);

        __syncthreads();
    }

    // ---- epilogue: bias + relu, then fp32 store or tf32 split store ----
    const bool do_split = (Clg != nullptr);
#pragma unroll
    for (int nt = 0; nt < 4; nt++) {
        int col = bn + wn + nt * 8 + 2 * tig;
        float b0 = bias[col], b1 = bias[col + 1];
#pragma unroll
        for (int mt = 0; mt < 4; mt++) {
            int row = bm + wm + mt * 16 + gid;
            float v0 = acc[mt][nt][0] + b0;
            float v1 = acc[mt][nt][1] + b1;
            float v2 = acc[mt][nt][2] + b0;
            float v3 = acc[mt][nt][3] + b1;
            if (do_relu) {
                v0 = fmaxf(v0, 0.f); v1 = fmaxf(v1, 0.f);
                v2 = fmaxf(v2, 0.f); v3 = fmaxf(v3, 0.f);
            }
            size_t o0 = (size_t)row * N + col;
            size_t o1 = (size_t)(row + 8) * N + col;
            if (do_split) {
                uint32_t h0, l0, h1, l1, h2, l2, h3, l3;
                split2(v0, h0, l0); split2(v1, h1, l1);
                split2(v2, h2, l2); split2(v3, h3, l3);
                *(float2*)(Cg  + o0) = make_float2(__uint_as_float(h0), __uint_as_float(h1));
                *(float2*)(Cg  + o1) = make_float2(__uint_as_float(h2), __uint_as_float(h3));
                *(float2*)(Clg + o0) = make_float2(__uint_as_float(l0), __uint_as_float(l1));
                *(float2*)(Clg + o1) = make_float2(__uint_as_float(l2), __uint_as_float(l3));
            } else {
                *(float2*)(Cg + o0) = make_float2(v0, v1);
                *(float2*)(Cg + o1) = make_float2(v2, v3);
            }
        }
    }
#undef ISSUE_STAGE
#undef MMA_K0
}

// ---------------- logits: warp-per-token, z-batched (5 slots) ------------------
__global__ __launch_bounds__(128) void logits_b(LogitsBatch lb)
{
    __shared__ float wt[NE][257];
    const int z = blockIdx.z;
    const float* __restrict__ X    = lb.X[z];
    const float* __restrict__ W    = lb.W[z];
    const float* __restrict__ bias = lb.bias[z];
    float* __restrict__ out        = lb.out[z];
    const int Kd = lb.Kd[z];

    const int tid = threadIdx.x;
    const int wid = tid >> 5;
    const int lane = tid & 31;
    const int tok = blockIdx.x * 4 + wid;

    float acc[NE];
#pragma unroll
    for (int e = 0; e < NE; e++) acc[e] = 0.f;

    const float* xrow = X + (size_t)tok * Kd;

    for (int c = 0; c < Kd; c += 256) {
#pragma unroll
        for (int l = 0; l < 8; l++) {
            int id = tid + l * 128;
            int k  = id >> 2;
            int e4 = (id & 3) << 2;
            float4 v = *(const float4*)(W + (size_t)(c + k) * NE + e4);
            wt[e4 + 0][k] = v.x;
            wt[e4 + 1][k] = v.y;
            wt[e4 + 2][k] = v.z;
            wt[e4 + 3][k] = v.w;
        }
        __syncthreads();
#pragma unroll
        for (int i = 0; i < 8; i++) {
            int kk = i * 32 + lane;
            float xv = xrow[c + kk];
#pragma unroll
            for (int e = 0; e < NE; e++)
                acc[e] = fmaf(xv, wt[e][kk], acc[e]);
        }
        __syncthreads();
    }
#pragma unroll
    for (int off = 16; off > 0; off >>= 1)
#pragma unroll
        for (int e = 0; e < NE; e++)
            acc[e] += __shfl_xor_sync(0xffffffffu, acc[e], off);
    if (lane == 0) {
#pragma unroll
        for (int e = 0; e < NE; e++)
            out[(size_t)tok * NE + e] = acc[e] + bias[e];
    }
}

// ---------------- router --------------------------------------------------------
__global__ __launch_bounds__(256) void router_kernel(
    const float* __restrict__ glog, const float* __restrict__ slog,
    float* __restrict__ out, float* __restrict__ partial)
{
    __shared__ float sh[256][NE];
    const int tid = threadIdx.x;
    const int tok = blockIdx.x * 256 + tid;

    float probs[NE];
    {
        float g[NE];
#pragma unroll
        for (int i = 0; i < NE; i++) g[i] = glog[(size_t)tok * NE + i];
        float mx = g[0];
#pragma unroll
        for (int i = 1; i < NE; i++) mx = fmaxf(mx, g[i]);
        float s = 0.f;
#pragma unroll
        for (int i = 0; i < NE; i++) { g[i] = expf(g[i] - mx); s += g[i]; }
        float inv = 0.7f / s;
#pragma unroll
        for (int i = 0; i < NE; i++) probs[i] = g[i] * inv;
    }
#pragma unroll
    for (int m = 0; m < NMOD; m++) {
        float g[NE];
#pragma unroll
        for (int i = 0; i < NE; i++)
            g[i] = slog[((size_t)m * TOKENS + tok) * NE + i];
        float mx = g[0];
#pragma unroll
        for (int i = 1; i < NE; i++) mx = fmaxf(mx, g[i]);
        float s = 0.f;
#pragma unroll
        for (int i = 0; i < NE; i++) { g[i] = expf(g[i] - mx); s += g[i]; }
        float inv = 0.15f / s;
#pragma unroll
        for (int i = 0; i < NE; i++) probs[i] += g[i] * inv;
    }

#pragma unroll
    for (int i = 0; i < NE; i++)
        out[RP_OFF + (size_t)tok * NE + i] = probs[i];

    unsigned used = 0;
    int idx[4]; float val[4]; float vsum = 0.f;
#pragma unroll
    for (int k = 0; k < 4; k++) {
        float best = -1.f; int bi = 0;
#pragma unroll
        for (int i = 0; i < NE; i++) {
            bool ok = !((used >> i) & 1u);
            if (ok && probs[i] > best) { best = probs[i]; bi = i; }
        }
        used |= (1u << bi);
        idx[k] = bi; val[k] = best; vsum += best;
    }
    float invv = 1.f / vsum;
#pragma unroll
    for (int k = 0; k < 4; k++) {
        size_t base = ((size_t)tok * NE + idx[k]) * CAP;
        out[base]         = 1.f;
        out[C_OFF + base] = val[k] * invv;
    }

#pragma unroll
    for (int i = 0; i < NE; i++) sh[tid][i] = probs[i];
    __syncthreads();
    if (tid < NE) {
        float s = 0.f;
        for (int i = 0; i < 256; i++) s += sh[i][tid];
        partial[blockIdx.x * NE + tid] = s;
    }
}

// ---------------- aux loss ------------------------------------------------------
__global__ void aux_kernel(const float* __restrict__ partial, float* __restrict__ out)
{
    const int tid = threadIdx.x;
    float v = 0.f;
    if (tid < NE) {
        float s = 0.f;
#pragma unroll
        for (int b = 0; b < 8; b++) s += partial[b * NE + tid];
        float mp = s * (1.f / (float)TOKENS);
        v = mp * logf(mp * (float)NE + 1e-9f);
    }
#pragma unroll
    for (int off = 16; off > 0; off >>= 1)
        v += __shfl_down_sync(0xffffffffu, v, off);
    if (tid == 0) out[AUX_OFF] = v;
}

// ---------------- launch --------------------------------------------------------
extern "C" void kernel_launch(void* const* d_in, const int* in_sizes, int n_in,
                              void* d_out, int out_size)
{
    const float* hs   = (const float*)d_in[0];
    const float* mimg = (const float*)d_in[1];
    const float* mgen = (const float*)d_in[2];
    const float* Wg1  = (const float*)d_in[3];
    const float* bg1  = (const float*)d_in[4];
    const float* Wg2  = (const float*)d_in[5];
    const float* bg2  = (const float*)d_in[6];
    const float* Wm1  = (const float*)d_in[7];
    const float* bm1  = (const float*)d_in[8];
    const float* Wm2  = (const float*)d_in[9];
    const float* bm2  = (const float*)d_in[10];
    const float* Ws1  = (const float*)d_in[11];
    const float* bs1  = (const float*)d_in[12];
    const float* Ws2  = (const float*)d_in[13];
    const float* bs2  = (const float*)d_in[14];
    float* out = (float*)d_out;

    float *HSh, *HSl, *MIh, *MIl, *MGh, *MGl;
    float *W1h, *W1l, *Wg1h, *Wg1l, *W2h, *W2l, *Ws1h, *Ws1l;
    float *T1h, *T1l, *T2h, *T2l, *T1g, *S1, *glog, *slog, *partial;
    cudaGetSymbolAddress((void**)&HSh,  g_HSh);  cudaGetSymbolAddress((void**)&HSl,  g_HSl);
    cudaGetSymbolAddress((void**)&MIh,  g_MIh);  cudaGetSymbolAddress((void**)&MIl,  g_MIl);
    cudaGetSymbolAddress((void**)&MGh,  g_MGh);  cudaGetSymbolAddress((void**)&MGl,  g_MGl);
    cudaGetSymbolAddress((void**)&W1h,  g_W1h);  cudaGetSymbolAddress((void**)&W1l,  g_W1l);
    cudaGetSymbolAddress((void**)&Wg1h, g_Wg1h); cudaGetSymbolAddress((void**)&Wg1l, g_Wg1l);
    cudaGetSymbolAddress((void**)&W2h,  g_W2h);  cudaGetSymbolAddress((void**)&W2l,  g_W2l);
    cudaGetSymbolAddress((void**)&Ws1h, g_Ws1h); cudaGetSymbolAddress((void**)&Ws1l, g_Ws1l);
    cudaGetSymbolAddress((void**)&T1h,  g_T1h);  cudaGetSymbolAddress((void**)&T1l,  g_T1l);
    cudaGetSymbolAddress((void**)&T2h,  g_T2h);  cudaGetSymbolAddress((void**)&T2l,  g_T2l);
    cudaGetSymbolAddress((void**)&T1g,  g_T1g);
    cudaGetSymbolAddress((void**)&S1,   g_S1);
    cudaGetSymbolAddress((void**)&glog, g_glog);
    cudaGetSymbolAddress((void**)&slog, g_slog);
    cudaGetSymbolAddress((void**)&partial, g_partial);

    cudaFuncSetAttribute(gemm_ps,
                         cudaFuncAttributeMaxDynamicSharedMemorySize, SMEM_BYTES);

    zero_kernel<<<4096, 256>>>((float4*)out, (int)(2 * C_OFF / 4));

    // 0. bulk split of all inputs (8 slots x 4M floats)
    {
        SplitSlices ss{};
        ss.src[0] = (const float4*)hs;   ss.hi[0] = (float4*)HSh;  ss.lo[0] = (float4*)HSl;
        ss.src[1] = (const float4*)mimg; ss.hi[1] = (float4*)MIh;  ss.lo[1] = (float4*)MIl;
        ss.src[2] = (const float4*)mgen; ss.hi[2] = (float4*)MGh;  ss.lo[2] = (float4*)MGl;
        ss.src[3] = (const float4*)Wm1;  ss.hi[3] = (float4*)W1h;  ss.lo[3] = (float4*)W1l;
        ss.src[4] = (const float4*)Wg1;  ss.hi[4] = (float4*)Wg1h; ss.lo[4] = (float4*)Wg1l;
        ss.src[5] = (const float4*)Wm2;  ss.hi[5] = (float4*)W2h;  ss.lo[5] = (float4*)W2l;
        ss.src[6] = (const float4*)Ws1;  ss.hi[6] = (float4*)Ws1h; ss.lo[6] = (float4*)Ws1l;
        ss.src[7] = (const float4*)(Ws1 + M4);
        ss.hi[7]  = (float4*)(Ws1h + M4);
        ss.lo[7]  = (float4*)(Ws1l + M4);
        dim3 grid(1024, 1, 8);
        split_b<<<grid, 256>>>(ss);
    }

    // L1: big1 (HS@Wm1 -> T1 split) x2 col-slices, big3 (HS@Wg1 -> T1g) x2, mid0, mid1.
    // All slices are 2048 x 1024 outputs -> grid (8, 16, 6).
    {
        GemmSlices gs{};
        gs.Ah[0] = HSh; gs.Al[0] = HSl; gs.Bh[0] = W1h; gs.Bl[0] = W1l;
        gs.bias[0] = bm1; gs.C[0] = T1h; gs.Cl[0] = T1l; gs.N[0] = HDIM; gs.bn0[0] = 0;
        gs.Ah[1] = HSh; gs.Al[1] = HSl; gs.Bh[1] = W1h; gs.Bl[1] = W1l;
        gs.bias[1] = bm1; gs.C[1] = T1h; gs.Cl[1] = T1l; gs.N[1] = HDIM; gs.bn0[1] = 1024;
        gs.Ah[2] = HSh; gs.Al[2] = HSl; gs.Bh[2] = Wg1h; gs.Bl[2] = Wg1l;
        gs.bias[2] = bg1; gs.C[2] = T1g; gs.Cl[2] = nullptr; gs.N[2] = HDIM; gs.bn0[2] = 0;
        gs.Ah[3] = HSh; gs.Al[3] = HSl; gs.Bh[3] = Wg1h; gs.Bl[3] = Wg1l;
        gs.bias[3] = bg1; gs.C[3] = T1g; gs.Cl[3] = nullptr; gs.N[3] = HDIM; gs.bn0[3] = 1024;
        gs.Ah[4] = MIh; gs.Al[4] = MIl; gs.Bh[4] = Ws1h; gs.Bl[4] = Ws1l;
        gs.bias[4] = bs1; gs.C[4] = S1; gs.Cl[4] = nullptr; gs.N[4] = H2DIM; gs.bn0[4] = 0;
        gs.Ah[5] = MGh; gs.Al[5] = MGl;
        gs.Bh[5] = Ws1h + (size_t)HDIM * H2DIM; gs.Bl[5] = Ws1l + (size_t)HDIM * H2DIM;
        gs.bias[5] = bs1 + H2DIM; gs.C[5] = S1 + (size_t)TOKENS * H2DIM;
        gs.Cl[5] = nullptr; gs.N[5] = H2DIM; gs.bn0[5] = 0;
        dim3 grid(8, 16, 6);
        gemm_ps<<<grid, 256, SMEM_BYTES>>>(gs, 1);
    }

    // L2: T2 = T1 @ Wm2 + bm2 (no relu) -> split planes. 2 column slices.
    {
        GemmSlices gs{};
        for (int s = 0; s < 2; s++) {
            gs.Ah[s] = T1h; gs.Al[s] = T1l; gs.Bh[s] = W2h; gs.Bl[s] = W2l;
            gs.bias[s] = bm2; gs.C[s] = T2h; gs.Cl[s] = T2l;
            gs.N[s] = HDIM; gs.bn0[s] = s * 1024;
        }
        dim3 grid(8, 16, 2);
        gemm_ps<<<grid, 256, SMEM_BYTES>>>(gs, 0);
    }

    // L3: mid2, mid3 (A = T2 planes) -> S1 fp32. relu=1.
    {
        GemmSlices gs{};
        for (int m = 2; m < 4; m++) {
            int zz = m - 2;
            gs.Ah[zz] = T2h; gs.Al[zz] = T2l;
            gs.Bh[zz] = Ws1h + (size_t)m * HDIM * H2DIM;
            gs.Bl[zz] = Ws1l + (size_t)m * HDIM * H2DIM;
            gs.bias[zz] = bs1 + (size_t)m * H2DIM;
            gs.C[zz]  = S1 + (size_t)m * TOKENS * H2DIM;
            gs.Cl[zz] = nullptr;
            gs.N[zz]  = H2DIM;
            gs.bn0[zz] = 0;
        }
        dim3 grid(8, 16, 2);
        gemm_ps<<<grid, 256, SMEM_BYTES>>>(gs, 1);
    }

    // L4: all 5 logits GEMMs in one launch
    {
        LogitsBatch lb{};
        lb.X[0] = T1g; lb.W[0] = Wg2; lb.bias[0] = bg2; lb.out[0] = glog;
        lb.Kd[0] = HDIM;
        for (int m = 0; m < 4; m++) {
            lb.X[m+1]    = S1 + (size_t)m * TOKENS * H2DIM;
            lb.W[m+1]    = Ws2 + (size_t)m * H2DIM * NE;
            lb.bias[m+1] = bs2 + (size_t)m * NE;
            lb.out[m+1]  = slog + (size_t)m * TOKENS * NE;
            lb.Kd[m+1]   = H2DIM;
        }
        dim3 grid(512, 1, 5);
        logits_b<<<grid, 128>>>(lb);
    }

    router_kernel<<<8, 256>>>(glog, slog, out, partial);
    aux_kernel<<<1, 32>>>(partial, out);
}

// round 17
// speedup vs baseline: 1.5893x; 1.5858x over previous
#include <cuda_runtime.h>
#include <cuda_fp16.h>
#include <math.h>
#include <stdint.h>

#define TOKENS 2048
#define HDIM   2048
#define H2DIM  1024
#define NE     16
#define NMOD   4
#define CAP    768
#define KD     2048

static constexpr long long C_OFF   = (long long)TOKENS * NE * CAP;
static constexpr long long RP_OFF  = 2 * C_OFF;
static constexpr long long AUX_OFF = RP_OFF + (long long)TOKENS * NE;

// ---------------- device scratch ---------------------------------------------
#define M4 (4 * 1024 * 1024)
// A-side half planes (token-major, row length 2048)
__device__ __half g_HSh[M4],  g_HSl[M4];
__device__ __half g_MIh[M4],  g_MIl[M4];
__device__ __half g_MGh[M4],  g_MGl[M4];
__device__ __half g_T1h[M4],  g_T1l[M4];
__device__ __half g_T2h[M4],  g_T2l[M4];
// B-side half planes, TRANSPOSED: [n][k=2048]
__device__ __half g_W1th[M4],  g_W1tl[M4];      // Wm1^T  (n=2048)
__device__ __half g_Wg1th[M4], g_Wg1tl[M4];     // Wg1^T  (n=2048)
__device__ __half g_W2th[M4],  g_W2tl[M4];      // Wm2^T  (n=2048)
__device__ __half g_Ws1th[2*M4], g_Ws1tl[2*M4]; // Ws1^T  (4 x n=1024)
// fp32 buffers
__device__ float g_T1g[M4];
__device__ float g_S1[NMOD * TOKENS * H2DIM];
__device__ float g_glog[TOKENS * NE];
__device__ float g_slog[NMOD * TOKENS * NE];
__device__ float g_partial[8 * NE];

struct ASlices {
    const float4* src[3];
    __half2*      hi[3];
    __half2*      lo[3];
};
struct WtSlices {
    const float* src[6];
    __half*      hi[6];
    __half*      lo[6];
    int          N[6];
};
struct GemmSlices {
    const __half *Ah[6], *Al[6], *Bh[6], *Bl[6];
    const float* bias[6];
    void*        C[6];
    void*        Cl[6];   // non-null -> C/Cl are half planes (split store)
    int          N[6];
    int          bn0[6];
};
struct LogitsBatch {
    const float* X[5];
    const float* W[5];
    const float* bias[5];
    float*       out[5];
    int          Kd[5];
};

// ---------------- helpers ------------------------------------------------------
__device__ __forceinline__ void mma_f16(float* c, const uint32_t* a, const uint32_t* b) {
    asm volatile(
        "mma.sync.aligned.m16n8k16.row.col.f32.f16.f16.f32 "
        "{%0,%1,%2,%3}, {%4,%5,%6,%7}, {%8,%9}, {%0,%1,%2,%3};"
        : "+f"(c[0]), "+f"(c[1]), "+f"(c[2]), "+f"(c[3])
        : "r"(a[0]), "r"(a[1]), "r"(a[2]), "r"(a[3]), "r"(b[0]), "r"(b[1]));
}

__device__ __forceinline__ void hsplit(float v, __half& h, __half& l) {
    h = __float2half_rn(v);
    l = __float2half_rn((v - __half2float(h)) * 2048.0f);
}

#define CP16(dst, src) \
    asm volatile("cp.async.cg.shared.global [%0], [%1], 16;" :: "r"(dst), "l"(src))
#define CP_COMMIT() asm volatile("cp.async.commit_group;" ::: "memory")
#define CP_WAIT1()  asm volatile("cp.async.wait_group 1;" ::: "memory")
#define CP_WAIT0()  asm volatile("cp.async.wait_group 0;" ::: "memory")

// ---------------- zero-fill -----------------------------------------------------
__global__ void zero_kernel(float4* __restrict__ p, int n4) {
    int i = blockIdx.x * blockDim.x + threadIdx.x;
    int stride = gridDim.x * blockDim.x;
    float4 z = make_float4(0.f, 0.f, 0.f, 0.f);
    for (; i < n4; i += stride) p[i] = z;
}

// ---------------- A-side split: fp32 -> half hi / half lo*2048 ------------------
__global__ void split_a(ASlices as) {
    const int z = blockIdx.z;
    const float4* __restrict__ src = as.src[z];
    __half2* __restrict__ hi = as.hi[z];
    __half2* __restrict__ lo = as.lo[z];
    const int n4 = M4 / 4;
    int i = blockIdx.x * blockDim.x + threadIdx.x;
    int stride = gridDim.x * blockDim.x;
    for (; i < n4; i += stride) {
        float4 v = src[i];
        __half h0, l0, h1, l1, h2, l2, h3, l3;
        hsplit(v.x, h0, l0); hsplit(v.y, h1, l1);
        hsplit(v.z, h2, l2); hsplit(v.w, h3, l3);
        hi[2 * i]     = __halves2half2(h0, h1);
        hi[2 * i + 1] = __halves2half2(h2, h3);
        lo[2 * i]     = __halves2half2(l0, l1);
        lo[2 * i + 1] = __halves2half2(l2, l3);
    }
}

// ---------------- W split + transpose: W[k][n] fp32 -> Wt[n][k] half -------------
__global__ void split_wt(WtSlices ws) {
    __shared__ float t[32][33];
    const int z = blockIdx.z;
    const float* __restrict__ W = ws.src[z];
    __half* __restrict__ dh = ws.hi[z];
    __half* __restrict__ dl = ws.lo[z];
    const int N = ws.N[z];

    const int k0 = blockIdx.x * 32;
    const int n0 = blockIdx.y * 32;
    if (n0 >= N) return;
    const int tx = threadIdx.x;   // 0..31
    const int ty = threadIdx.y;   // 0..7

#pragma unroll
    for (int j = 0; j < 4; j++)
        t[ty + 8 * j][tx] = W[(size_t)(k0 + ty + 8 * j) * N + n0 + tx];
    __syncthreads();
#pragma unroll
    for (int j = 0; j < 4; j++) {
        int n = n0 + ty + 8 * j;
        int k = k0 + tx;
        float v = t[tx][ty + 8 * j];
        __half h, l;
        hsplit(v, h, l);
        dh[(size_t)n * KD + k] = h;
        dl[(size_t)n * KD + k] = l;
    }
}

// ---------------- HMMA 3xFP16 GEMM (scaled split), 128x64, 3-stage, 2 CTA/SM ----
// C = act(A @ W + bias). BK=32 (2 k16 steps), 256 threads, 8 warps of 32x32.
// acc1 = Ahi*Bhi ; acc2 = Alo_s*Bhi + Ahi*Blo_s ; final = acc1 + acc2/2048.
// Smem per stage (uint32 words): Ah[128][20]=2560, Al=2560, Bh[64][20]=1280, Bl=1280.
#define AL_OFS 2560
#define BH_OFS 5120
#define BL_OFS 6400
#define STG_W  7680
#define STG_B  (STG_W * 4)           // 30720
#define SMEM_BYTES (3 * STG_B)       // 92160 -> 2 CTAs/SM

__global__ __launch_bounds__(256, 2) void gemm_h3(GemmSlices gs, int do_relu)
{
    extern __shared__ uint32_t sm[];

    const int z = blockIdx.z;
    const __half* __restrict__ Ahg = gs.Ah[z];
    const __half* __restrict__ Alg = gs.Al[z];
    const __half* __restrict__ Bhg = gs.Bh[z];
    const __half* __restrict__ Blg = gs.Bl[z];
    const float* __restrict__ bias = gs.bias[z];
    const int N  = gs.N[z];
    const int bn = gs.bn0[z] + blockIdx.x * 64;
    const int bm = blockIdx.y * 128;

    const int tid  = threadIdx.x;
    const int wid  = tid >> 5;
    const int lane = tid & 31;
    const int gid  = lane >> 2;
    const int tig  = lane & 3;
    const int wm   = (wid & 3) * 32;
    const int wn   = (wid >> 2) * 32;

    const uint32_t smb = (uint32_t)__cvta_generic_to_shared(sm);

#define ISSUE_STAGE(s, kb) do {                                                  \
    uint32_t sb = smb + (uint32_t)(s) * STG_B;                                   \
    size_t ka = (size_t)(kb) * 32;                                               \
    _Pragma("unroll")                                                            \
    for (int l = 0; l < 2; l++) {                                                \
        int c = tid + 256 * l;                                                   \
        int r = c >> 2, sg = c & 3;                                              \
        uint32_t d = sb + (uint32_t)(r * 20 + sg * 4) * 4;                       \
        size_t go = (size_t)(bm + r) * KD + ka + sg * 8;                         \
        CP16(d, Ahg + go);                                                       \
        CP16(d + AL_OFS * 4, Alg + go);                                          \
    }                                                                            \
    {                                                                            \
        int n = tid >> 2, sg = tid & 3;                                          \
        uint32_t d = sb + BH_OFS * 4 + (uint32_t)(n * 20 + sg * 4) * 4;          \
        size_t go = (size_t)(bn + n) * KD + ka + sg * 8;                         \
        CP16(d, Bhg + go);                                                       \
        CP16(d + (BL_OFS - BH_OFS) * 4, Blg + go);                               \
    }                                                                            \
    CP_COMMIT();                                                                 \
} while (0)

#define MMA_WB(wb) do {                                                          \
    uint32_t fah[2][4], fal[2][4], fbh[4][2], fbl[4][2];                         \
    _Pragma("unroll")                                                            \
    for (int mt = 0; mt < 2; mt++) {                                             \
        int rb = (wm + mt * 16 + gid) * 20 + (wb) + tig;                         \
        fah[mt][0] = AH[rb];                                                     \
        fah[mt][1] = AH[rb + 160];                                               \
        fah[mt][2] = AH[rb + 4];                                                 \
        fah[mt][3] = AH[rb + 164];                                               \
    }                                                                            \
    _Pragma("unroll")                                                            \
    for (int nt = 0; nt < 4; nt++) {                                             \
        int cb = (wn + nt * 8 + gid) * 20 + (wb) + tig;                          \
        fbh[nt][0] = BH[cb];                                                     \
        fbh[nt][1] = BH[cb + 4];                                                 \
    }                                                                            \
    _Pragma("unroll")                                                            \
    for (int mt = 0; mt < 2; mt++)                                               \
        _Pragma("unroll")                                                        \
        for (int nt = 0; nt < 4; nt++)                                           \
            mma_f16(acc[mt][nt], fah[mt], fbh[nt]);                              \
    _Pragma("unroll")                                                            \
    for (int mt = 0; mt < 2; mt++) {                                             \
        int rb = (wm + mt * 16 + gid) * 20 + (wb) + tig;                         \
        fal[mt][0] = ALo[rb];                                                    \
        fal[mt][1] = ALo[rb + 160];                                              \
        fal[mt][2] = ALo[rb + 4];                                                \
        fal[mt][3] = ALo[rb + 164];                                              \
    }                                                                            \
    _Pragma("unroll")                                                            \
    for (int mt = 0; mt < 2; mt++)                                               \
        _Pragma("unroll")                                                        \
        for (int nt = 0; nt < 4; nt++)                                           \
            mma_f16(acc2[mt][nt], fal[mt], fbh[nt]);                             \
    _Pragma("unroll")                                                            \
    for (int nt = 0; nt < 4; nt++) {                                             \
        int cb = (wn + nt * 8 + gid) * 20 + (wb) + tig;                          \
        fbl[nt][0] = BLo[cb];                                                    \
        fbl[nt][1] = BLo[cb + 4];                                                \
    }                                                                            \
    _Pragma("unroll")                                                            \
    for (int mt = 0; mt < 2; mt++)                                               \
        _Pragma("unroll")                                                        \
        for (int nt = 0; nt < 4; nt++)                                           \
            mma_f16(acc2[mt][nt], fah[mt], fbl[nt]);                             \
} while (0)

    float acc[2][4][4], acc2[2][4][4];
#pragma unroll
    for (int mt = 0; mt < 2; mt++)
#pragma unroll
        for (int nt = 0; nt < 4; nt++)
#pragma unroll
            for (int r = 0; r < 4; r++) { acc[mt][nt][r] = 0.f; acc2[mt][nt][r] = 0.f; }

    const int KT = KD / 32;   // 64

    ISSUE_STAGE(0, 0);
    ISSUE_STAGE(1, 1);

    for (int kb = 0; kb < KT; kb++) {
        if (kb < KT - 1) { CP_WAIT1(); } else { CP_WAIT0(); }
        __syncthreads();

        if (kb + 2 < KT) ISSUE_STAGE((kb + 2) % 3, kb + 2);

        const uint32_t* st  = sm + (kb % 3) * STG_W;
        const uint32_t* AH  = st;
        const uint32_t* ALo = st + AL_OFS;
        const uint32_t* BH  = st + BH_OFS;
        const uint32_t* BLo = st + BL_OFS;

        MMA_WB(0);
        MMA_WB(8);

        __syncthreads();
    }

    // ---- epilogue: combine scaled planes, bias, relu, store ----
    const bool do_split = (gs.Cl[z] != nullptr);
    const float inv2048 = 4.8828125e-4f;
#pragma unroll
    for (int nt = 0; nt < 4; nt++) {
        int col = bn + wn + nt * 8 + 2 * tig;
        float b0 = bias[col], b1 = bias[col + 1];
#pragma unroll
        for (int mt = 0; mt < 2; mt++) {
            int row = bm + wm + mt * 16 + gid;
            float v0 = acc[mt][nt][0] + acc2[mt][nt][0] * inv2048 + b0;
            float v1 = acc[mt][nt][1] + acc2[mt][nt][1] * inv2048 + b1;
            float v2 = acc[mt][nt][2] + acc2[mt][nt][2] * inv2048 + b0;
            float v3 = acc[mt][nt][3] + acc2[mt][nt][3] * inv2048 + b1;
            if (do_relu) {
                v0 = fmaxf(v0, 0.f); v1 = fmaxf(v1, 0.f);
                v2 = fmaxf(v2, 0.f); v3 = fmaxf(v3, 0.f);
            }
            size_t o0 = (size_t)row * N + col;
            size_t o1 = (size_t)(row + 8) * N + col;
            if (do_split) {
                __half* Chg = (__half*)gs.C[z];
                __half* Clg = (__half*)gs.Cl[z];
                __half h0, l0, h1, l1, h2, l2, h3, l3;
                hsplit(v0, h0, l0); hsplit(v1, h1, l1);
                hsplit(v2, h2, l2); hsplit(v3, h3, l3);
                *(__half2*)(Chg + o0) = __halves2half2(h0, h1);
                *(__half2*)(Chg + o1) = __halves2half2(h2, h3);
                *(__half2*)(Clg + o0) = __halves2half2(l0, l1);
                *(__half2*)(Clg + o1) = __halves2half2(l2, l3);
            } else {
                float* Cg = (float*)gs.C[z];
                *(float2*)(Cg + o0) = make_float2(v0, v1);
                *(float2*)(Cg + o1) = make_float2(v2, v3);
            }
        }
    }
#undef ISSUE_STAGE
#undef MMA_WB
}

// ---------------- logits: warp-per-token, z-batched (5 slots) ------------------
__global__ __launch_bounds__(128) void logits_b(LogitsBatch lb)
{
    __shared__ float wt[NE][257];
    const int z = blockIdx.z;
    const float* __restrict__ X    = lb.X[z];
    const float* __restrict__ W    = lb.W[z];
    const float* __restrict__ bias = lb.bias[z];
    float* __restrict__ out        = lb.out[z];
    const int Kd = lb.Kd[z];

    const int tid = threadIdx.x;
    const int wid = tid >> 5;
    const int lane = tid & 31;
    const int tok = blockIdx.x * 4 + wid;

    float acc[NE];
#pragma unroll
    for (int e = 0; e < NE; e++) acc[e] = 0.f;

    const float* xrow = X + (size_t)tok * Kd;

    for (int c = 0; c < Kd; c += 256) {
#pragma unroll
        for (int l = 0; l < 8; l++) {
            int id = tid + l * 128;
            int k  = id >> 2;
            int e4 = (id & 3) << 2;
            float4 v = *(const float4*)(W + (size_t)(c + k) * NE + e4);
            wt[e4 + 0][k] = v.x;
            wt[e4 + 1][k] = v.y;
            wt[e4 + 2][k] = v.z;
            wt[e4 + 3][k] = v.w;
        }
        __syncthreads();
#pragma unroll
        for (int i = 0; i < 8; i++) {
            int kk = i * 32 + lane;
            float xv = xrow[c + kk];
#pragma unroll
            for (int e = 0; e < NE; e++)
                acc[e] = fmaf(xv, wt[e][kk], acc[e]);
        }
        __syncthreads();
    }
#pragma unroll
    for (int off = 16; off > 0; off >>= 1)
#pragma unroll
        for (int e = 0; e < NE; e++)
            acc[e] += __shfl_xor_sync(0xffffffffu, acc[e], off);
    if (lane == 0) {
#pragma unroll
        for (int e = 0; e < NE; e++)
            out[(size_t)tok * NE + e] = acc[e] + bias[e];
    }
}

// ---------------- router --------------------------------------------------------
__global__ __launch_bounds__(256) void router_kernel(
    const float* __restrict__ glog, const float* __restrict__ slog,
    float* __restrict__ out, float* __restrict__ partial)
{
    __shared__ float sh[256][NE];
    const int tid = threadIdx.x;
    const int tok = blockIdx.x * 256 + tid;

    float probs[NE];
    {
        float g[NE];
#pragma unroll
        for (int i = 0; i < NE; i++) g[i] = glog[(size_t)tok * NE + i];
        float mx = g[0];
#pragma unroll
        for (int i = 1; i < NE; i++) mx = fmaxf(mx, g[i]);
        float s = 0.f;
#pragma unroll
        for (int i = 0; i < NE; i++) { g[i] = expf(g[i] - mx); s += g[i]; }
        float inv = 0.7f / s;
#pragma unroll
        for (int i = 0; i < NE; i++) probs[i] = g[i] * inv;
    }
#pragma unroll
    for (int m = 0; m < NMOD; m++) {
        float g[NE];
#pragma unroll
        for (int i = 0; i < NE; i++)
            g[i] = slog[((size_t)m * TOKENS + tok) * NE + i];
        float mx = g[0];
#pragma unroll
        for (int i = 1; i < NE; i++) mx = fmaxf(mx, g[i]);
        float s = 0.f;
#pragma unroll
        for (int i = 0; i < NE; i++) { g[i] = expf(g[i] - mx); s += g[i]; }
        float inv = 0.15f / s;
#pragma unroll
        for (int i = 0; i < NE; i++) probs[i] += g[i] * inv;
    }

#pragma unroll
    for (int i = 0; i < NE; i++)
        out[RP_OFF + (size_t)tok * NE + i] = probs[i];

    unsigned used = 0;
    int idx[4]; float val[4]; float vsum = 0.f;
#pragma unroll
    for (int k = 0; k < 4; k++) {
        float best = -1.f; int bi = 0;
#pragma unroll
        for (int i = 0; i < NE; i++) {
            bool ok = !((used >> i) & 1u);
            if (ok && probs[i] > best) { best = probs[i]; bi = i; }
        }
        used |= (1u << bi);
        idx[k] = bi; val[k] = best; vsum += best;
    }
    float invv = 1.f / vsum;
#pragma unroll
    for (int k = 0; k < 4; k++) {
        size_t base = ((size_t)tok * NE + idx[k]) * CAP;
        out[base]         = 1.f;
        out[C_OFF + base] = val[k] * invv;
    }

#pragma unroll
    for (int i = 0; i < NE; i++) sh[tid][i] = probs[i];
    __syncthreads();
    if (tid < NE) {
        float s = 0.f;
        for (int i = 0; i < 256; i++) s += sh[i][tid];
        partial[blockIdx.x * NE + tid] = s;
    }
}

// ---------------- aux loss ------------------------------------------------------
__global__ void aux_kernel(const float* __restrict__ partial, float* __restrict__ out)
{
    const int tid = threadIdx.x;
    float v = 0.f;
    if (tid < NE) {
        float s = 0.f;
#pragma unroll
        for (int b = 0; b < 8; b++) s += partial[b * NE + tid];
        float mp = s * (1.f / (float)TOKENS);
        v = mp * logf(mp * (float)NE + 1e-9f);
    }
#pragma unroll
    for (int off = 16; off > 0; off >>= 1)
        v += __shfl_down_sync(0xffffffffu, v, off);
    if (tid == 0) out[AUX_OFF] = v;
}

// ---------------- launch --------------------------------------------------------
extern "C" void kernel_launch(void* const* d_in, const int* in_sizes, int n_in,
                              void* d_out, int out_size)
{
    const float* hs   = (const float*)d_in[0];
    const float* mimg = (const float*)d_in[1];
    const float* mgen = (const float*)d_in[2];
    const float* Wg1  = (const float*)d_in[3];
    const float* bg1  = (const float*)d_in[4];
    const float* Wg2  = (const float*)d_in[5];
    const float* bg2  = (const float*)d_in[6];
    const float* Wm1  = (const float*)d_in[7];
    const float* bm1  = (const float*)d_in[8];
    const float* Wm2  = (const float*)d_in[9];
    const float* bm2  = (const float*)d_in[10];
    const float* Ws1  = (const float*)d_in[11];
    const float* bs1  = (const float*)d_in[12];
    const float* Ws2  = (const float*)d_in[13];
    const float* bs2  = (const float*)d_in[14];
    float* out = (float*)d_out;

    __half *HSh, *HSl, *MIh, *MIl, *MGh, *MGl;
    __half *W1th, *W1tl, *Wg1th, *Wg1tl, *W2th, *W2tl, *Ws1th, *Ws1tl;
    __half *T1h, *T1l, *T2h, *T2l;
    float *T1g, *S1, *glog, *slog, *partial;
    cudaGetSymbolAddress((void**)&HSh,   g_HSh);   cudaGetSymbolAddress((void**)&HSl,   g_HSl);
    cudaGetSymbolAddress((void**)&MIh,   g_MIh);   cudaGetSymbolAddress((void**)&MIl,   g_MIl);
    cudaGetSymbolAddress((void**)&MGh,   g_MGh);   cudaGetSymbolAddress((void**)&MGl,   g_MGl);
    cudaGetSymbolAddress((void**)&W1th,  g_W1th);  cudaGetSymbolAddress((void**)&W1tl,  g_W1tl);
    cudaGetSymbolAddress((void**)&Wg1th, g_Wg1th); cudaGetSymbolAddress((void**)&Wg1tl, g_Wg1tl);
    cudaGetSymbolAddress((void**)&W2th,  g_W2th);  cudaGetSymbolAddress((void**)&W2tl,  g_W2tl);
    cudaGetSymbolAddress((void**)&Ws1th, g_Ws1th); cudaGetSymbolAddress((void**)&Ws1tl, g_Ws1tl);
    cudaGetSymbolAddress((void**)&T1h,   g_T1h);   cudaGetSymbolAddress((void**)&T1l,   g_T1l);
    cudaGetSymbolAddress((void**)&T2h,   g_T2h);   cudaGetSymbolAddress((void**)&T2l,   g_T2l);
    cudaGetSymbolAddress((void**)&T1g,   g_T1g);
    cudaGetSymbolAddress((void**)&S1,    g_S1);
    cudaGetSymbolAddress((void**)&glog,  g_glog);
    cudaGetSymbolAddress((void**)&slog,  g_slog);
    cudaGetSymbolAddress((void**)&partial, g_partial);

    cudaFuncSetAttribute(gemm_h3,
                         cudaFuncAttributeMaxDynamicSharedMemorySize, SMEM_BYTES);

    zero_kernel<<<4096, 256>>>((float4*)out, (int)(2 * C_OFF / 4));

    // 0a. A-side splits (hs, mimg, mgen)
    {
        ASlices as{};
        as.src[0] = (const float4*)hs;   as.hi[0] = (__half2*)HSh; as.lo[0] = (__half2*)HSl;
        as.src[1] = (const float4*)mimg; as.hi[1] = (__half2*)MIh; as.lo[1] = (__half2*)MIl;
        as.src[2] = (const float4*)mgen; as.hi[2] = (__half2*)MGh; as.lo[2] = (__half2*)MGl;
        dim3 grid(1024, 1, 3);
        split_a<<<grid, 256>>>(as);
    }
    // 0b. W splits + transpose (Wm1, Wg1, Wm2, Ws1 m0..3)
    {
        WtSlices ws{};
        ws.src[0] = Wm1; ws.hi[0] = W1th;  ws.lo[0] = W1tl;  ws.N[0] = HDIM;
        ws.src[1] = Wg1; ws.hi[1] = Wg1th; ws.lo[1] = Wg1tl; ws.N[1] = HDIM;
        ws.src[2] = Wm2; ws.hi[2] = W2th;  ws.lo[2] = W2tl;  ws.N[2] = HDIM;
        for (int m = 0; m < 4; m++) {
            ws.src[3 + m > 5 ? 5 : 3 + m] = ws.src[3 + m > 5 ? 5 : 3 + m]; // noop guard
        }
        // slots 3..5 hold Ws1 m0..2; m3 launched separately below? No — pack m0,m1,m2 here
        ws.src[3] = Ws1;                               ws.hi[3] = Ws1th;
        ws.lo[3] = Ws1tl;                              ws.N[3] = H2DIM;
        ws.src[4] = Ws1 + (size_t)HDIM * H2DIM;        ws.hi[4] = Ws1th + (size_t)H2DIM * KD;
        ws.lo[4] = Ws1tl + (size_t)H2DIM * KD;         ws.N[4] = H2DIM;
        ws.src[5] = Ws1 + 2 * (size_t)HDIM * H2DIM;    ws.hi[5] = Ws1th + 2 * (size_t)H2DIM * KD;
        ws.lo[5] = Ws1tl + 2 * (size_t)H2DIM * KD;     ws.N[5] = H2DIM;
        dim3 grid(64, 64, 6);
        split_wt<<<grid, dim3(32, 8)>>>(ws);
        // Ws1 m3
        WtSlices w2{};
        w2.src[0] = Ws1 + 3 * (size_t)HDIM * H2DIM;    w2.hi[0] = Ws1th + 3 * (size_t)H2DIM * KD;
        w2.lo[0] = Ws1tl + 3 * (size_t)H2DIM * KD;     w2.N[0] = H2DIM;
        dim3 g2(64, 32, 1);
        split_wt<<<g2, dim3(32, 8)>>>(w2);
    }

    // L1: big1 (HS@Wm1 -> T1 half split) x2, big3 (HS@Wg1 -> T1g fp32) x2, mid0, mid1.
    {
        GemmSlices gs{};
        gs.Ah[0] = HSh; gs.Al[0] = HSl; gs.Bh[0] = W1th; gs.Bl[0] = W1tl;
        gs.bias[0] = bm1; gs.C[0] = T1h; gs.Cl[0] = T1l; gs.N[0] = HDIM; gs.bn0[0] = 0;
        gs.Ah[1] = HSh; gs.Al[1] = HSl; gs.Bh[1] = W1th; gs.Bl[1] = W1tl;
        gs.bias[1] = bm1; gs.C[1] = T1h; gs.Cl[1] = T1l; gs.N[1] = HDIM; gs.bn0[1] = 1024;
        gs.Ah[2] = HSh; gs.Al[2] = HSl; gs.Bh[2] = Wg1th; gs.Bl[2] = Wg1tl;
        gs.bias[2] = bg1; gs.C[2] = T1g; gs.Cl[2] = nullptr; gs.N[2] = HDIM; gs.bn0[2] = 0;
        gs.Ah[3] = HSh; gs.Al[3] = HSl; gs.Bh[3] = Wg1th; gs.Bl[3] = Wg1tl;
        gs.bias[3] = bg1; gs.C[3] = T1g; gs.Cl[3] = nullptr; gs.N[3] = HDIM; gs.bn0[3] = 1024;
        gs.Ah[4] = MIh; gs.Al[4] = MIl; gs.Bh[4] = Ws1th; gs.Bl[4] = Ws1tl;
        gs.bias[4] = bs1; gs.C[4] = S1; gs.Cl[4] = nullptr; gs.N[4] = H2DIM; gs.bn0[4] = 0;
        gs.Ah[5] = MGh; gs.Al[5] = MGl;
        gs.Bh[5] = Ws1th + (size_t)H2DIM * KD; gs.Bl[5] = Ws1tl + (size_t)H2DIM * KD;
        gs.bias[5] = bs1 + H2DIM; gs.C[5] = S1 + (size_t)TOKENS * H2DIM;
        gs.Cl[5] = nullptr; gs.N[5] = H2DIM; gs.bn0[5] = 0;
        dim3 grid(16, 16, 6);
        gemm_h3<<<grid, 256, SMEM_BYTES>>>(gs, 1);
    }

    // L2: T2 = T1 @ Wm2 + bm2 (no relu) -> half split planes. 2 column slices.
    {
        GemmSlices gs{};
        for (int s = 0; s < 2; s++) {
            gs.Ah[s] = T1h; gs.Al[s] = T1l; gs.Bh[s] = W2th; gs.Bl[s] = W2tl;
            gs.bias[s] = bm2; gs.C[s] = T2h; gs.Cl[s] = T2l;
            gs.N[s] = HDIM; gs.bn0[s] = s * 1024;
        }
        dim3 grid(16, 16, 2);
        gemm_h3<<<grid, 256, SMEM_BYTES>>>(gs, 0);
    }

    // L3: mid2, mid3 (A = T2 planes) -> S1 fp32. relu=1.
    {
        GemmSlices gs{};
        for (int m = 2; m < 4; m++) {
            int zz = m - 2;
            gs.Ah[zz] = T2h; gs.Al[zz] = T2l;
            gs.Bh[zz] = Ws1th + (size_t)m * H2DIM * KD;
            gs.Bl[zz] = Ws1tl + (size_t)m * H2DIM * KD;
            gs.bias[zz] = bs1 + (size_t)m * H2DIM;
            gs.C[zz]  = S1 + (size_t)m * TOKENS * H2DIM;
            gs.Cl[zz] = nullptr;
            gs.N[zz]  = H2DIM;
            gs.bn0[zz] = 0;
        }
        dim3 grid(16, 16, 2);
        gemm_h3<<<grid, 256, SMEM_BYTES>>>(gs, 1);
    }

    // L4: all 5 logits GEMMs in one launch
    {
        LogitsBatch lb{};
        lb.X[0] = T1g; lb.W[0] = Wg2; lb.bias[0] = bg2; lb.out[0] = glog;
        lb.Kd[0] = HDIM;
        for (int m = 0; m < 4; m++) {
            lb.X[m+1]    = S1 + (size_t)m * TOKENS * H2DIM;
            lb.W[m+1]    = Ws2 + (size_t)m * H2DIM * NE;
            lb.bias[m+1] = bs2 + (size_t)m * NE;
            lb.out[m+1]  = slog + (size_t)m * TOKENS * NE;
            lb.Kd[m+1]   = H2DIM;
        }
        dim3 grid(512, 1, 5);
        logits_b<<<grid, 128>>>(lb);
    }

    router_kernel<<<8, 256>>>(glog, slog, out, partial);
    aux_kernel<<<1, 32>>>(partial, out);
}